// round 4
// baseline (speedup 1.0000x reference)
#include <cuda_runtime.h>
#include <cuda_bf16.h>
#include <math_constants.h>

// Problem constants
#define BATCH 8
#define CIN   512
#define NPIX  4096          // 64*64
#define OCQKV 1536          // 3 * INNER
#define INNER 512
#define HEADS 8
#define DH    64
#define INV_N (1.0f/4096.0f)

// Scratch (allocation-free: __device__ globals)
__device__ __align__(16) float g_qkv [(size_t)BATCH * OCQKV * NPIX];  // 192 MB
__device__ __align__(16) float g_ctx [(size_t)BATCH * HEADS * DH * DH]; // 1 MB
__device__ __align__(16) float g_mid [(size_t)BATCH * INNER * NPIX];  // 64 MB
__device__ __align__(16) float g_proj[(size_t)BATCH * INNER * NPIX];  // 64 MB

// ---------------------------------------------------------------------------
// Tiled fp32 GEMM: Y[b] = A(MxK) * X[b](KxN) (+bias per row). All dims divide tiles.
// BM=BN=128, BK=16, 256 threads, 8x8 per-thread microtile.
// ---------------------------------------------------------------------------
__global__ __launch_bounds__(256) void gemm_tiled(
    const float* __restrict__ A,   // [M,K] row-major (no batch)
    const float* __restrict__ Xg,  // [BATCH][K][N]
    float* __restrict__ Yg,        // [BATCH][M][N]
    int M, int K, int Nn,
    const float* __restrict__ bias)
{
    const int b  = blockIdx.z;
    const float* X = Xg + (size_t)b * K * Nn;
    float* Y       = Yg + (size_t)b * M * Nn;
    const int m0 = blockIdx.y * 128;
    const int n0 = blockIdx.x * 128;
    const int tid = threadIdx.x;
    const int ty = tid >> 4;       // 0..15
    const int tx = tid & 15;       // 0..15

    __shared__ float As[16][128];
    __shared__ float Bs[16][128];

    float acc[8][8];
#pragma unroll
    for (int i = 0; i < 8; i++)
#pragma unroll
        for (int j = 0; j < 8; j++) acc[i][j] = 0.f;

    for (int k0 = 0; k0 < K; k0 += 16) {
        // A tile: 128 rows x 16 cols = 512 float4, store transposed As[k][m]
#pragma unroll
        for (int it = 0; it < 2; it++) {
            int idx = tid + it * 256;
            int row = idx >> 2;            // 0..127
            int c4  = (idx & 3) * 4;       // 0,4,8,12
            float4 av = *reinterpret_cast<const float4*>(
                &A[(size_t)(m0 + row) * K + k0 + c4]);
            As[c4 + 0][row] = av.x;
            As[c4 + 1][row] = av.y;
            As[c4 + 2][row] = av.z;
            As[c4 + 3][row] = av.w;
        }
        // B tile: 16 rows x 128 cols = 512 float4, direct
#pragma unroll
        for (int it = 0; it < 2; it++) {
            int idx = tid + it * 256;
            int row = idx >> 5;            // 0..15
            int c4  = (idx & 31) * 4;      // 0..124
            *reinterpret_cast<float4*>(&Bs[row][c4]) =
                *reinterpret_cast<const float4*>(&X[(size_t)(k0 + row) * Nn + n0 + c4]);
        }
        __syncthreads();

#pragma unroll
        for (int k = 0; k < 16; k++) {
            float a[8], bb[8];
            *reinterpret_cast<float4*>(a)     = *reinterpret_cast<float4*>(&As[k][ty * 8]);
            *reinterpret_cast<float4*>(a + 4) = *reinterpret_cast<float4*>(&As[k][ty * 8 + 4]);
            *reinterpret_cast<float4*>(bb)    = *reinterpret_cast<float4*>(&Bs[k][tx * 8]);
            *reinterpret_cast<float4*>(bb + 4)= *reinterpret_cast<float4*>(&Bs[k][tx * 8 + 4]);
#pragma unroll
            for (int i = 0; i < 8; i++)
#pragma unroll
                for (int j = 0; j < 8; j++)
                    acc[i][j] += a[i] * bb[j];
        }
        __syncthreads();
    }

#pragma unroll
    for (int i = 0; i < 8; i++) {
        int m = m0 + ty * 8 + i;
        float bv = bias ? bias[m] : 0.f;
#pragma unroll
        for (int j = 0; j < 8; j += 4) {
            float4 o;
            o.x = acc[i][j + 0] + bv;
            o.y = acc[i][j + 1] + bv;
            o.z = acc[i][j + 2] + bv;
            o.w = acc[i][j + 3] + bv;
            *reinterpret_cast<float4*>(&Y[(size_t)m * Nn + n0 + tx * 8 + j]) = o;
        }
    }
}

// ---------------------------------------------------------------------------
// softmax over d (64 values, stride N) for the q block, then scale by 1/8.
// One thread per (b,h,n). In-place on g_qkv.
// ---------------------------------------------------------------------------
__global__ __launch_bounds__(256) void softmax_q_kernel()
{
    const int n = blockIdx.x * 256 + threadIdx.x;
    const int h = blockIdx.y;
    const int b = blockIdx.z;
    float* base = g_qkv + ((size_t)b * OCQKV + h * DH) * NPIX + n;

    float v[64];
#pragma unroll
    for (int d = 0; d < 64; d++) v[d] = base[(size_t)d * NPIX];
    float mx = v[0];
#pragma unroll
    for (int d = 1; d < 64; d++) mx = fmaxf(mx, v[d]);
    float s = 0.f;
#pragma unroll
    for (int d = 0; d < 64; d++) { v[d] = __expf(v[d] - mx); s += v[d]; }
    float inv = 1.f / (s * 8.f);   // includes 1/sqrt(DH)
#pragma unroll
    for (int d = 0; d < 64; d++) base[(size_t)d * NPIX] = v[d] * inv;
}

// ---------------------------------------------------------------------------
// softmax over N (4096 contiguous) for the k block. One block per row.
// ---------------------------------------------------------------------------
__global__ __launch_bounds__(256) void softmax_k_kernel()
{
    const int row = blockIdx.x;        // 0..4095 = b*512 + ch
    const int b   = row >> 9;
    const int ch  = row & 511;
    float* base = g_qkv + ((size_t)b * OCQKV + INNER + ch) * NPIX;
    const int tid = threadIdx.x;
    const int lane = tid & 31, wid = tid >> 5;

    __shared__ float red[8];
    __shared__ float bcast;

    float vals[16];
#pragma unroll
    for (int j = 0; j < 16; j++) vals[j] = base[tid + j * 256];

    float m = vals[0];
#pragma unroll
    for (int j = 1; j < 16; j++) m = fmaxf(m, vals[j]);
#pragma unroll
    for (int off = 16; off > 0; off >>= 1)
        m = fmaxf(m, __shfl_xor_sync(0xffffffff, m, off));
    if (lane == 0) red[wid] = m;
    __syncthreads();
    if (tid == 0) {
        float mm = red[0];
#pragma unroll
        for (int w = 1; w < 8; w++) mm = fmaxf(mm, red[w]);
        bcast = mm;
    }
    __syncthreads();
    const float mx = bcast;

    float s = 0.f;
#pragma unroll
    for (int j = 0; j < 16; j++) { vals[j] = __expf(vals[j] - mx); s += vals[j]; }
#pragma unroll
    for (int off = 16; off > 0; off >>= 1)
        s += __shfl_xor_sync(0xffffffff, s, off);
    if (lane == 0) red[wid] = s;
    __syncthreads();
    if (tid == 0) {
        float ss = 0.f;
#pragma unroll
        for (int w = 0; w < 8; w++) ss += red[w];
        bcast = 1.f / ss;
    }
    __syncthreads();
    const float inv = bcast;
#pragma unroll
    for (int j = 0; j < 16; j++) base[tid + j * 256] = vals[j] * inv;
}

__global__ __launch_bounds__(256) void zero_ctx_kernel()
{
    int i = blockIdx.x * 256 + threadIdx.x;
    if (i < BATCH * HEADS * DH * DH) g_ctx[i] = 0.f;
}

// ---------------------------------------------------------------------------
// context[b,h,d,e] += sum_{n in chunk} k_sm[d,n] * (v[e,n]/N)
// grid (8 n-chunks of 512, HEADS, BATCH); 16x16 threads, 4x4 micro.
// ---------------------------------------------------------------------------
__global__ __launch_bounds__(256) void context_kernel()
{
    const int nchunk = blockIdx.x;
    const int h = blockIdx.y;
    const int b = blockIdx.z;
    const float* kbase = g_qkv + ((size_t)b * OCQKV + INNER     + h * DH) * NPIX;
    const float* vbase = g_qkv + ((size_t)b * OCQKV + 2 * INNER + h * DH) * NPIX;

    __shared__ float Ks[64][65];   // [n][d]
    __shared__ float Vs[64][65];   // [n][e]

    const int tid = threadIdx.x;
    const int ty = tid >> 4, tx = tid & 15;
    float acc[4][4];
#pragma unroll
    for (int i = 0; i < 4; i++)
#pragma unroll
        for (int j = 0; j < 4; j++) acc[i][j] = 0.f;

    for (int nt = 0; nt < 8; nt++) {
        const int n0 = nchunk * 512 + nt * 64;
#pragma unroll
        for (int it = 0; it < 4; it++) {
            int idx = tid + it * 256;
            int r  = idx >> 4;            // 0..63 (d or e)
            int c4 = (idx & 15) * 4;      // n offset
            float4 kv = *reinterpret_cast<const float4*>(&kbase[(size_t)r * NPIX + n0 + c4]);
            Ks[c4 + 0][r] = kv.x; Ks[c4 + 1][r] = kv.y;
            Ks[c4 + 2][r] = kv.z; Ks[c4 + 3][r] = kv.w;
            float4 vv = *reinterpret_cast<const float4*>(&vbase[(size_t)r * NPIX + n0 + c4]);
            Vs[c4 + 0][r] = vv.x * INV_N; Vs[c4 + 1][r] = vv.y * INV_N;
            Vs[c4 + 2][r] = vv.z * INV_N; Vs[c4 + 3][r] = vv.w * INV_N;
        }
        __syncthreads();
#pragma unroll
        for (int nn = 0; nn < 64; nn++) {
            float kr[4], vr[4];
#pragma unroll
            for (int i = 0; i < 4; i++) kr[i] = Ks[nn][ty * 4 + i];
#pragma unroll
            for (int j = 0; j < 4; j++) vr[j] = Vs[nn][tx * 4 + j];
#pragma unroll
            for (int i = 0; i < 4; i++)
#pragma unroll
                for (int j = 0; j < 4; j++) acc[i][j] += kr[i] * vr[j];
        }
        __syncthreads();
    }
    float* cbase = g_ctx + (size_t)(b * HEADS + h) * DH * DH;
#pragma unroll
    for (int i = 0; i < 4; i++)
#pragma unroll
        for (int j = 0; j < 4; j++)
            atomicAdd(&cbase[(ty * 4 + i) * DH + tx * 4 + j], acc[i][j]);
}

// ---------------------------------------------------------------------------
// out_mid[b, h*64+e, n] = sum_d ctx[b,h,d,e] * q_sm[b,h,d,n]
// One thread per (b,h,n), 64 accumulators.
// ---------------------------------------------------------------------------
__global__ __launch_bounds__(256) void apply_kernel()
{
    const int n = blockIdx.x * 256 + threadIdx.x;
    const int h = blockIdx.y;
    const int b = blockIdx.z;

    __shared__ float ctxs[64][64];
    const float* csrc = g_ctx + (size_t)(b * HEADS + h) * DH * DH;
    for (int i = threadIdx.x; i < 4096; i += 256)
        (&ctxs[0][0])[i] = csrc[i];
    __syncthreads();

    const float* qbase = g_qkv + ((size_t)b * OCQKV + h * DH) * NPIX + n;
    float acc[64];
#pragma unroll
    for (int e = 0; e < 64; e++) acc[e] = 0.f;

#pragma unroll 4
    for (int d = 0; d < 64; d++) {
        float qd = qbase[(size_t)d * NPIX];
#pragma unroll
        for (int e = 0; e < 64; e++) acc[e] += ctxs[d][e] * qd;
    }
    float* obase = g_mid + ((size_t)b * INNER + h * DH) * NPIX + n;
#pragma unroll
    for (int e = 0; e < 64; e++) obase[(size_t)e * NPIX] = acc[e];
}

// ---------------------------------------------------------------------------
// LayerNorm over channel dim (512, stride N), no affine, eps=1e-5.
// ---------------------------------------------------------------------------
__global__ __launch_bounds__(256) void ln_kernel(float* __restrict__ out)
{
    const int n = blockIdx.x * 256 + threadIdx.x;
    const int b = blockIdx.y;
    const float* base = g_proj + (size_t)b * INNER * NPIX + n;

    float s = 0.f, s2 = 0.f;
#pragma unroll 8
    for (int c = 0; c < 512; c++) {
        float v = base[(size_t)c * NPIX];
        s += v; s2 += v * v;
    }
    const float mu  = s * (1.f / 512.f);
    const float var = s2 * (1.f / 512.f) - mu * mu;
    const float inv = rsqrtf(var + 1e-5f);
    float* ob = out + (size_t)b * INNER * NPIX + n;
#pragma unroll 8
    for (int c = 0; c < 512; c++)
        ob[(size_t)c * NPIX] = (base[(size_t)c * NPIX] - mu) * inv;
}

// ---------------------------------------------------------------------------
extern "C" void kernel_launch(void* const* d_in, const int* in_sizes, int n_in,
                              void* d_out, int out_size)
{
    (void)in_sizes; (void)n_in; (void)out_size;
    const float* x     = (const float*)d_in[0];   // [8,512,64,64]
    const float* w_qkv = (const float*)d_in[1];   // [1536,512]
    const float* w_out = (const float*)d_in[2];   // [512,512]
    const float* b_out = (const float*)d_in[3];   // [512]
    float* out = (float*)d_out;                   // [8,512,64,64]

    float* qkv_p;  cudaGetSymbolAddress((void**)&qkv_p,  g_qkv);
    float* mid_p;  cudaGetSymbolAddress((void**)&mid_p,  g_mid);
    float* proj_p; cudaGetSymbolAddress((void**)&proj_p, g_proj);

    zero_ctx_kernel<<<(BATCH * HEADS * DH * DH + 255) / 256, 256>>>();
    // qkv = w_qkv @ x  : M=1536, K=512, N=4096 per batch
    gemm_tiled<<<dim3(NPIX / 128, OCQKV / 128, BATCH), 256>>>(
        w_qkv, x, qkv_p, OCQKV, CIN, NPIX, nullptr);
    softmax_q_kernel<<<dim3(NPIX / 256, HEADS, BATCH), 256>>>();
    softmax_k_kernel<<<BATCH * INNER, 256>>>();
    context_kernel<<<dim3(8, HEADS, BATCH), 256>>>();
    apply_kernel<<<dim3(NPIX / 256, HEADS, BATCH), 256>>>();
    // proj = w_out @ mid + b_out : M=512, K=512, N=4096 per batch
    gemm_tiled<<<dim3(NPIX / 128, INNER / 128, BATCH), 256>>>(
        w_out, mid_p, proj_p, INNER, INNER, NPIX, b_out);
    ln_kernel<<<dim3(NPIX / 256, BATCH), 256>>>(out);
}

// round 7
// speedup vs baseline: 1.9300x; 1.9300x over previous
#include <cuda_runtime.h>
#include <cuda_bf16.h>
#include <math_constants.h>
#include <cstdint>

// Problem constants
#define BATCH 8
#define CIN   512
#define NPIX  4096          // 64*64
#define OCQKV 1536          // 3 * INNER
#define INNER 512
#define HEADS 8
#define DH    64
#define INV_N (1.0f/4096.0f)

// Scratch (allocation-free: __device__ globals)
__device__ __align__(16) float g_qkv [(size_t)BATCH * OCQKV * NPIX];  // 192 MB
__device__ __align__(16) float g_ctx [(size_t)BATCH * HEADS * DH * DH]; // 1 MB
__device__ __align__(16) float g_mid [(size_t)BATCH * INNER * NPIX];  // 64 MB
__device__ __align__(16) float g_proj[(size_t)BATCH * INNER * NPIX];  // 64 MB

// ---------------------------------------------------------------------------
// tf32 helpers
// ---------------------------------------------------------------------------
__device__ __forceinline__ uint32_t f2tf32(float f) {
    uint32_t r;
    asm("cvt.rna.tf32.f32 %0, %1;" : "=r"(r) : "f"(f));
    return r;
}

__device__ __forceinline__ void mma_tf32(float* c, const uint32_t* a, const uint32_t* b) {
    asm volatile(
        "mma.sync.aligned.m16n8k8.row.col.f32.tf32.tf32.f32 "
        "{%0,%1,%2,%3}, {%4,%5,%6,%7}, {%8,%9}, {%0,%1,%2,%3};\n"
        : "+f"(c[0]), "+f"(c[1]), "+f"(c[2]), "+f"(c[3])
        : "r"(a[0]), "r"(a[1]), "r"(a[2]), "r"(a[3]), "r"(b[0]), "r"(b[1]));
}

// ---------------------------------------------------------------------------
// Tensor-core tf32 GEMM: Y[b] = A(MxK) * X[b](KxN) (+bias per row).
// BM=BN=128, BK=32, 256 threads (8 warps as 4x2), warp tile 32x64,
// mma m16n8k8 (2 M-tiles x 8 N-tiles per warp). Smem stride 136 -> all
// fragment LDS conflict-free (bank = 8c + r, 32 distinct lanes).
// ---------------------------------------------------------------------------
__global__ __launch_bounds__(256) void gemm_tf32(
    const float* __restrict__ A,   // [M,K] row-major (no batch)
    const float* __restrict__ Xg,  // [BATCH][K][N]
    float* __restrict__ Yg,        // [BATCH][M][N]
    int M, int K, int Nn,
    const float* __restrict__ bias)
{
    const int b  = blockIdx.z;
    const float* X = Xg + (size_t)b * K * Nn;
    float* Y       = Yg + (size_t)b * M * Nn;
    const int m0 = blockIdx.y * 128;
    const int n0 = blockIdx.x * 128;
    const int tid  = threadIdx.x;
    const int lane = tid & 31;
    const int warp = tid >> 5;
    const int wm = (warp & 3) * 32;   // 4 warps along M
    const int wn = (warp >> 2) * 64;  // 2 warps along N
    const int r = lane >> 2;          // 0..7
    const int c = lane & 3;           // 0..3

    __shared__ uint32_t As[32][136];  // [k][m], tf32 bits
    __shared__ uint32_t Bs[32][136];  // [k][n], tf32 bits

    float acc[2][8][4];
#pragma unroll
    for (int mt = 0; mt < 2; mt++)
#pragma unroll
        for (int nt = 0; nt < 8; nt++)
#pragma unroll
            for (int i = 0; i < 4; i++) acc[mt][nt][i] = 0.f;

    for (int k0 = 0; k0 < K; k0 += 32) {
        // A tile: 128(m) x 32(k). m-consecutive threads -> conflict-free STS.
#pragma unroll
        for (int it = 0; it < 4; it++) {
            int idx = tid + it * 256;          // 0..1023
            int m   = idx & 127;
            int k4  = (idx >> 7) * 4;          // 0,4,...,28
            float4 v = *reinterpret_cast<const float4*>(
                &A[(size_t)(m0 + m) * K + k0 + k4]);
            As[k4 + 0][m] = f2tf32(v.x);
            As[k4 + 1][m] = f2tf32(v.y);
            As[k4 + 2][m] = f2tf32(v.z);
            As[k4 + 3][m] = f2tf32(v.w);
        }
        // B tile: 32(k) x 128(n), fully coalesced rows.
#pragma unroll
        for (int it = 0; it < 4; it++) {
            int idx = tid + it * 256;
            int kk  = idx >> 5;                // 0..31
            int n4  = (idx & 31) * 4;
            float4 v = *reinterpret_cast<const float4*>(
                &X[(size_t)(k0 + kk) * Nn + n0 + n4]);
            Bs[kk][n4 + 0] = f2tf32(v.x);
            Bs[kk][n4 + 1] = f2tf32(v.y);
            Bs[kk][n4 + 2] = f2tf32(v.z);
            Bs[kk][n4 + 3] = f2tf32(v.w);
        }
        __syncthreads();

#pragma unroll
        for (int ks = 0; ks < 4; ks++) {
            const int kc = ks * 8;
            uint32_t af[2][4];
#pragma unroll
            for (int mt = 0; mt < 2; mt++) {
                int mb = wm + mt * 16 + r;
                af[mt][0] = As[kc + c][mb];
                af[mt][1] = As[kc + c][mb + 8];
                af[mt][2] = As[kc + c + 4][mb];
                af[mt][3] = As[kc + c + 4][mb + 8];
            }
            uint32_t bf[8][2];
#pragma unroll
            for (int nt = 0; nt < 8; nt++) {
                int nb = wn + nt * 8 + r;
                bf[nt][0] = Bs[kc + c][nb];
                bf[nt][1] = Bs[kc + c + 4][nb];
            }
#pragma unroll
            for (int mt = 0; mt < 2; mt++)
#pragma unroll
                for (int nt = 0; nt < 8; nt++)
                    mma_tf32(acc[mt][nt], af[mt], bf[nt]);
        }
        __syncthreads();
    }

    // Epilogue: c0,c1 -> (row, 2c), (row, 2c+1); c2,c3 -> row+8.
#pragma unroll
    for (int mt = 0; mt < 2; mt++) {
        const int mrow = m0 + wm + mt * 16 + r;
        const float bv0 = bias ? bias[mrow]     : 0.f;
        const float bv1 = bias ? bias[mrow + 8] : 0.f;
#pragma unroll
        for (int nt = 0; nt < 8; nt++) {
            const int ncol = n0 + wn + nt * 8 + 2 * c;
            float2 o0, o1;
            o0.x = acc[mt][nt][0] + bv0; o0.y = acc[mt][nt][1] + bv0;
            o1.x = acc[mt][nt][2] + bv1; o1.y = acc[mt][nt][3] + bv1;
            *reinterpret_cast<float2*>(&Y[(size_t)mrow * Nn + ncol]) = o0;
            *reinterpret_cast<float2*>(&Y[(size_t)(mrow + 8) * Nn + ncol]) = o1;
        }
    }
}

// ---------------------------------------------------------------------------
// softmax over d (64 values, stride N) for the q block, then scale by 1/8.
// ---------------------------------------------------------------------------
__global__ __launch_bounds__(256) void softmax_q_kernel()
{
    const int n = blockIdx.x * 256 + threadIdx.x;
    const int h = blockIdx.y;
    const int b = blockIdx.z;
    float* base = g_qkv + ((size_t)b * OCQKV + h * DH) * NPIX + n;

    float v[64];
#pragma unroll
    for (int d = 0; d < 64; d++) v[d] = base[(size_t)d * NPIX];
    float mx = v[0];
#pragma unroll
    for (int d = 1; d < 64; d++) mx = fmaxf(mx, v[d]);
    float s = 0.f;
#pragma unroll
    for (int d = 0; d < 64; d++) { v[d] = __expf(v[d] - mx); s += v[d]; }
    float inv = 1.f / (s * 8.f);   // includes 1/sqrt(DH)
#pragma unroll
    for (int d = 0; d < 64; d++) base[(size_t)d * NPIX] = v[d] * inv;
}

// ---------------------------------------------------------------------------
// softmax over N (4096 contiguous) for the k block. One block per row.
// ---------------------------------------------------------------------------
__global__ __launch_bounds__(256) void softmax_k_kernel()
{
    const int row = blockIdx.x;        // 0..4095 = b*512 + ch
    const int b   = row >> 9;
    const int ch  = row & 511;
    float* base = g_qkv + ((size_t)b * OCQKV + INNER + ch) * NPIX;
    const int tid = threadIdx.x;
    const int lane = tid & 31, wid = tid >> 5;

    __shared__ float red[8];
    __shared__ float bcast;

    float vals[16];
#pragma unroll
    for (int j = 0; j < 16; j++) vals[j] = base[tid + j * 256];

    float m = vals[0];
#pragma unroll
    for (int j = 1; j < 16; j++) m = fmaxf(m, vals[j]);
#pragma unroll
    for (int off = 16; off > 0; off >>= 1)
        m = fmaxf(m, __shfl_xor_sync(0xffffffff, m, off));
    if (lane == 0) red[wid] = m;
    __syncthreads();
    if (tid == 0) {
        float mm = red[0];
#pragma unroll
        for (int w = 1; w < 8; w++) mm = fmaxf(mm, red[w]);
        bcast = mm;
    }
    __syncthreads();
    const float mx = bcast;

    float s = 0.f;
#pragma unroll
    for (int j = 0; j < 16; j++) { vals[j] = __expf(vals[j] - mx); s += vals[j]; }
#pragma unroll
    for (int off = 16; off > 0; off >>= 1)
        s += __shfl_xor_sync(0xffffffff, s, off);
    if (lane == 0) red[wid] = s;
    __syncthreads();
    if (tid == 0) {
        float ss = 0.f;
#pragma unroll
        for (int w = 0; w < 8; w++) ss += red[w];
        bcast = 1.f / ss;
    }
    __syncthreads();
    const float inv = bcast;
#pragma unroll
    for (int j = 0; j < 16; j++) base[tid + j * 256] = vals[j] * inv;
}

__global__ __launch_bounds__(256) void zero_ctx_kernel()
{
    int i = blockIdx.x * 256 + threadIdx.x;
    if (i < BATCH * HEADS * DH * DH) g_ctx[i] = 0.f;
}

// ---------------------------------------------------------------------------
// context[b,h,d,e] += sum_{n in chunk} k_sm[d,n] * (v[e,n]/N)
// ---------------------------------------------------------------------------
__global__ __launch_bounds__(256) void context_kernel()
{
    const int nchunk = blockIdx.x;
    const int h = blockIdx.y;
    const int b = blockIdx.z;
    const float* kbase = g_qkv + ((size_t)b * OCQKV + INNER     + h * DH) * NPIX;
    const float* vbase = g_qkv + ((size_t)b * OCQKV + 2 * INNER + h * DH) * NPIX;

    __shared__ float Ks[64][65];   // [n][d]
    __shared__ float Vs[64][65];   // [n][e]

    const int tid = threadIdx.x;
    const int ty = tid >> 4, tx = tid & 15;
    float acc[4][4];
#pragma unroll
    for (int i = 0; i < 4; i++)
#pragma unroll
        for (int j = 0; j < 4; j++) acc[i][j] = 0.f;

    for (int nt = 0; nt < 8; nt++) {
        const int n0 = nchunk * 512 + nt * 64;
#pragma unroll
        for (int it = 0; it < 4; it++) {
            int idx = tid + it * 256;
            int r  = idx >> 4;            // 0..63 (d or e)
            int c4 = (idx & 15) * 4;      // n offset
            float4 kv = *reinterpret_cast<const float4*>(&kbase[(size_t)r * NPIX + n0 + c4]);
            Ks[c4 + 0][r] = kv.x; Ks[c4 + 1][r] = kv.y;
            Ks[c4 + 2][r] = kv.z; Ks[c4 + 3][r] = kv.w;
            float4 vv = *reinterpret_cast<const float4*>(&vbase[(size_t)r * NPIX + n0 + c4]);
            Vs[c4 + 0][r] = vv.x * INV_N; Vs[c4 + 1][r] = vv.y * INV_N;
            Vs[c4 + 2][r] = vv.z * INV_N; Vs[c4 + 3][r] = vv.w * INV_N;
        }
        __syncthreads();
#pragma unroll
        for (int nn = 0; nn < 64; nn++) {
            float kr[4], vr[4];
#pragma unroll
            for (int i = 0; i < 4; i++) kr[i] = Ks[nn][ty * 4 + i];
#pragma unroll
            for (int j = 0; j < 4; j++) vr[j] = Vs[nn][tx * 4 + j];
#pragma unroll
            for (int i = 0; i < 4; i++)
#pragma unroll
                for (int j = 0; j < 4; j++) acc[i][j] += kr[i] * vr[j];
        }
        __syncthreads();
    }
    float* cbase = g_ctx + (size_t)(b * HEADS + h) * DH * DH;
#pragma unroll
    for (int i = 0; i < 4; i++)
#pragma unroll
        for (int j = 0; j < 4; j++)
            atomicAdd(&cbase[(ty * 4 + i) * DH + tx * 4 + j], acc[i][j]);
}

// ---------------------------------------------------------------------------
// out_mid[b, h*64+e, n] = sum_d ctx[b,h,d,e] * q_sm[b,h,d,n]
// ---------------------------------------------------------------------------
__global__ __launch_bounds__(256) void apply_kernel()
{
    const int n = blockIdx.x * 256 + threadIdx.x;
    const int h = blockIdx.y;
    const int b = blockIdx.z;

    __shared__ float ctxs[64][64];
    const float* csrc = g_ctx + (size_t)(b * HEADS + h) * DH * DH;
    for (int i = threadIdx.x; i < 4096; i += 256)
        (&ctxs[0][0])[i] = csrc[i];
    __syncthreads();

    const float* qbase = g_qkv + ((size_t)b * OCQKV + h * DH) * NPIX + n;
    float acc[64];
#pragma unroll
    for (int e = 0; e < 64; e++) acc[e] = 0.f;

#pragma unroll 4
    for (int d = 0; d < 64; d++) {
        float qd = qbase[(size_t)d * NPIX];
#pragma unroll
        for (int e = 0; e < 64; e++) acc[e] += ctxs[d][e] * qd;
    }
    float* obase = g_mid + ((size_t)b * INNER + h * DH) * NPIX + n;
#pragma unroll
    for (int e = 0; e < 64; e++) obase[(size_t)e * NPIX] = acc[e];
}

// ---------------------------------------------------------------------------
// LayerNorm over channel dim (512, stride N), no affine, eps=1e-5.
// ---------------------------------------------------------------------------
__global__ __launch_bounds__(256) void ln_kernel(float* __restrict__ out)
{
    const int n = blockIdx.x * 256 + threadIdx.x;
    const int b = blockIdx.y;
    const float* base = g_proj + (size_t)b * INNER * NPIX + n;

    float s = 0.f, s2 = 0.f;
#pragma unroll 8
    for (int c = 0; c < 512; c++) {
        float v = base[(size_t)c * NPIX];
        s += v; s2 += v * v;
    }
    const float mu  = s * (1.f / 512.f);
    const float var = s2 * (1.f / 512.f) - mu * mu;
    const float inv = rsqrtf(var + 1e-5f);
    float* ob = out + (size_t)b * INNER * NPIX + n;
#pragma unroll 8
    for (int c = 0; c < 512; c++)
        ob[(size_t)c * NPIX] = (base[(size_t)c * NPIX] - mu) * inv;
}

// ---------------------------------------------------------------------------
extern "C" void kernel_launch(void* const* d_in, const int* in_sizes, int n_in,
                              void* d_out, int out_size)
{
    (void)in_sizes; (void)n_in; (void)out_size;
    const float* x     = (const float*)d_in[0];   // [8,512,64,64]
    const float* w_qkv = (const float*)d_in[1];   // [1536,512]
    const float* w_out = (const float*)d_in[2];   // [512,512]
    const float* b_out = (const float*)d_in[3];   // [512]
    float* out = (float*)d_out;                   // [8,512,64,64]

    float* qkv_p;  cudaGetSymbolAddress((void**)&qkv_p,  g_qkv);
    float* mid_p;  cudaGetSymbolAddress((void**)&mid_p,  g_mid);
    float* proj_p; cudaGetSymbolAddress((void**)&proj_p, g_proj);

    zero_ctx_kernel<<<(BATCH * HEADS * DH * DH + 255) / 256, 256>>>();
    // qkv = w_qkv @ x  : M=1536, K=512, N=4096 per batch
    gemm_tf32<<<dim3(NPIX / 128, OCQKV / 128, BATCH), 256>>>(
        w_qkv, x, qkv_p, OCQKV, CIN, NPIX, nullptr);
    softmax_q_kernel<<<dim3(NPIX / 256, HEADS, BATCH), 256>>>();
    softmax_k_kernel<<<BATCH * INNER, 256>>>();
    context_kernel<<<dim3(8, HEADS, BATCH), 256>>>();
    apply_kernel<<<dim3(NPIX / 256, HEADS, BATCH), 256>>>();
    // proj = w_out @ mid + b_out : M=512, K=512, N=4096 per batch
    gemm_tf32<<<dim3(NPIX / 128, INNER / 128, BATCH), 256>>>(
        w_out, mid_p, proj_p, INNER, INNER, NPIX, b_out);
    ln_kernel<<<dim3(NPIX / 256, BATCH), 256>>>(out);
}

// round 8
// speedup vs baseline: 2.7745x; 1.4375x over previous
#include <cuda_runtime.h>
#include <cuda_bf16.h>
#include <math_constants.h>
#include <cstdint>

// Problem constants
#define BATCH 8
#define CIN   512
#define NPIX  4096          // 64*64
#define OCQKV 1536          // 3 * INNER
#define INNER 512
#define HEADS 8
#define DH    64
#define INV_N (1.0f/4096.0f)

// Scratch (allocation-free: __device__ globals)
__device__ __align__(16) float g_qkv [(size_t)BATCH * OCQKV * NPIX];  // 192 MB
__device__ __align__(16) float g_ctx [(size_t)BATCH * HEADS * DH * DH]; // 1 MB
__device__ __align__(16) float g_mid [(size_t)BATCH * INNER * NPIX];  // 64 MB
__device__ __align__(16) float g_proj[(size_t)BATCH * INNER * NPIX];  // 64 MB
__device__ __align__(16) float g_wqkv_t[(size_t)CIN * OCQKV];         // 3 MB  [K,M]
__device__ __align__(16) float g_wout_t[(size_t)INNER * INNER];       // 1 MB  [K,M]

// ---------------------------------------------------------------------------
__device__ __forceinline__ void cp_async16(void* smem, const void* gmem) {
    uint32_t s = (uint32_t)__cvta_generic_to_shared(smem);
    asm volatile("cp.async.cg.shared.global [%0], [%1], 16;" :: "r"(s), "l"(gmem));
}

__device__ __forceinline__ void mma_tf32(float* c, const uint32_t* a, const uint32_t* b) {
    asm volatile(
        "mma.sync.aligned.m16n8k8.row.col.f32.tf32.tf32.f32 "
        "{%0,%1,%2,%3}, {%4,%5,%6,%7}, {%8,%9}, {%0,%1,%2,%3};\n"
        : "+f"(c[0]), "+f"(c[1]), "+f"(c[2]), "+f"(c[3])
        : "r"(a[0]), "r"(a[1]), "r"(a[2]), "r"(a[3]), "r"(b[0]), "r"(b[1]));
}

// ---------------------------------------------------------------------------
// 32x32-tiled transpose: out[c][r] = in[r][c]. block (32,8).
// ---------------------------------------------------------------------------
__global__ __launch_bounds__(256) void transpose_kernel(
    const float* __restrict__ in, float* __restrict__ out, int R, int C)
{
    __shared__ float t[32][33];
    const int r0 = blockIdx.y * 32, c0 = blockIdx.x * 32;
    const int x = threadIdx.x, y = threadIdx.y;
#pragma unroll
    for (int i = 0; i < 32; i += 8)
        t[y + i][x] = in[(size_t)(r0 + y + i) * C + c0 + x];
    __syncthreads();
#pragma unroll
    for (int i = 0; i < 32; i += 8)
        out[(size_t)(c0 + y + i) * R + r0 + x] = t[x][y + i];
}

// ---------------------------------------------------------------------------
// Pipelined tensor-core tf32 GEMM: Y[b] = A(MxK) * X[b](KxN) (+bias).
// A supplied TRANSPOSED as At[K][M]. BM=BN=128, BK=32, double-buffered
// cp.async. 8 warps (4x2), warp tile 32x64, mma m16n8k8. fp32 bits are fed
// directly to HMMA.TF32 (HW truncation). Smem stride 136 -> conflict-free
// fragment LDS.
// ---------------------------------------------------------------------------
__global__ __launch_bounds__(256) void gemm_tf32_pipe(
    const float* __restrict__ At,  // [K,M]
    const float* __restrict__ Xg,  // [BATCH][K][N]
    float* __restrict__ Yg,        // [BATCH][M][N]
    int M, int K, int Nn,
    const float* __restrict__ bias)
{
    const int b  = blockIdx.z;
    const float* X = Xg + (size_t)b * K * Nn;
    float* Y       = Yg + (size_t)b * M * Nn;
    const int m0 = blockIdx.y * 128;
    const int n0 = blockIdx.x * 128;
    const int tid  = threadIdx.x;
    const int lane = tid & 31;
    const int warp = tid >> 5;
    const int wm = (warp & 3) * 32;   // 4 warps along M
    const int wn = (warp >> 2) * 64;  // 2 warps along N
    const int r = lane >> 2;          // 0..7
    const int c = lane & 3;           // 0..3

    __shared__ float As[2][32][136];  // [k][m]
    __shared__ float Bs[2][32][136];  // [k][n]

    const int NIT = K >> 5;           // K/32

    float acc[2][8][4];
#pragma unroll
    for (int mt = 0; mt < 2; mt++)
#pragma unroll
        for (int nt = 0; nt < 8; nt++)
#pragma unroll
            for (int i = 0; i < 4; i++) acc[mt][nt][i] = 0.f;

    // prologue: stage 0
    {
        const float* a_src = At + (size_t)0 * M + m0;
        const float* b_src = X  + (size_t)0 * Nn + n0;
#pragma unroll
        for (int u = 0; u < 4; u++) {
            int idx = tid + u * 256;
            int kk  = idx >> 5;
            int c4  = (idx & 31) * 4;
            cp_async16(&As[0][kk][c4], a_src + (size_t)kk * M  + c4);
            cp_async16(&Bs[0][kk][c4], b_src + (size_t)kk * Nn + c4);
        }
        asm volatile("cp.async.commit_group;");
    }

    for (int it = 0; it < NIT; it++) {
        if (it + 1 < NIT) {
            const int nb = (it + 1) & 1;
            const float* a_src = At + (size_t)(it + 1) * 32 * M + m0;
            const float* b_src = X  + (size_t)(it + 1) * 32 * Nn + n0;
#pragma unroll
            for (int u = 0; u < 4; u++) {
                int idx = tid + u * 256;
                int kk  = idx >> 5;
                int c4  = (idx & 31) * 4;
                cp_async16(&As[nb][kk][c4], a_src + (size_t)kk * M  + c4);
                cp_async16(&Bs[nb][kk][c4], b_src + (size_t)kk * Nn + c4);
            }
            asm volatile("cp.async.commit_group;");
            asm volatile("cp.async.wait_group 1;");
        } else {
            asm volatile("cp.async.wait_group 0;");
        }
        __syncthreads();

        const int cb = it & 1;
#pragma unroll
        for (int ks = 0; ks < 4; ks++) {
            const int kc = ks * 8;
            uint32_t af[2][4];
#pragma unroll
            for (int mt = 0; mt < 2; mt++) {
                int mb = wm + mt * 16 + r;
                af[mt][0] = __float_as_uint(As[cb][kc + c][mb]);
                af[mt][1] = __float_as_uint(As[cb][kc + c][mb + 8]);
                af[mt][2] = __float_as_uint(As[cb][kc + c + 4][mb]);
                af[mt][3] = __float_as_uint(As[cb][kc + c + 4][mb + 8]);
            }
            uint32_t bf[8][2];
#pragma unroll
            for (int nt = 0; nt < 8; nt++) {
                int nb2 = wn + nt * 8 + r;
                bf[nt][0] = __float_as_uint(Bs[cb][kc + c][nb2]);
                bf[nt][1] = __float_as_uint(Bs[cb][kc + c + 4][nb2]);
            }
#pragma unroll
            for (int mt = 0; mt < 2; mt++)
#pragma unroll
                for (int nt = 0; nt < 8; nt++)
                    mma_tf32(acc[mt][nt], af[mt], bf[nt]);
        }
        __syncthreads();
    }

    // Epilogue: c0,c1 -> (row, 2c), (row, 2c+1); c2,c3 -> row+8.
#pragma unroll
    for (int mt = 0; mt < 2; mt++) {
        const int mrow = m0 + wm + mt * 16 + r;
        const float bv0 = bias ? bias[mrow]     : 0.f;
        const float bv1 = bias ? bias[mrow + 8] : 0.f;
#pragma unroll
        for (int nt = 0; nt < 8; nt++) {
            const int ncol = n0 + wn + nt * 8 + 2 * c;
            float2 o0, o1;
            o0.x = acc[mt][nt][0] + bv0; o0.y = acc[mt][nt][1] + bv0;
            o1.x = acc[mt][nt][2] + bv1; o1.y = acc[mt][nt][3] + bv1;
            *reinterpret_cast<float2*>(&Y[(size_t)mrow * Nn + ncol]) = o0;
            *reinterpret_cast<float2*>(&Y[(size_t)(mrow + 8) * Nn + ncol]) = o1;
        }
    }
}

// ---------------------------------------------------------------------------
// softmax over N (4096 contiguous) for the k block. One block per row.
// ---------------------------------------------------------------------------
__global__ __launch_bounds__(256) void softmax_k_kernel()
{
    const int row = blockIdx.x;        // 0..4095 = b*512 + ch
    const int b   = row >> 9;
    const int ch  = row & 511;
    float* base = g_qkv + ((size_t)b * OCQKV + INNER + ch) * NPIX;
    const int tid = threadIdx.x;
    const int lane = tid & 31, wid = tid >> 5;

    __shared__ float red[8];
    __shared__ float bcast;

    float vals[16];
#pragma unroll
    for (int j = 0; j < 16; j++) vals[j] = base[tid + j * 256];

    float m = vals[0];
#pragma unroll
    for (int j = 1; j < 16; j++) m = fmaxf(m, vals[j]);
#pragma unroll
    for (int off = 16; off > 0; off >>= 1)
        m = fmaxf(m, __shfl_xor_sync(0xffffffff, m, off));
    if (lane == 0) red[wid] = m;
    __syncthreads();
    if (tid == 0) {
        float mm = red[0];
#pragma unroll
        for (int w = 1; w < 8; w++) mm = fmaxf(mm, red[w]);
        bcast = mm;
    }
    __syncthreads();
    const float mx = bcast;

    float s = 0.f;
#pragma unroll
    for (int j = 0; j < 16; j++) { vals[j] = __expf(vals[j] - mx); s += vals[j]; }
#pragma unroll
    for (int off = 16; off > 0; off >>= 1)
        s += __shfl_xor_sync(0xffffffff, s, off);
    if (lane == 0) red[wid] = s;
    __syncthreads();
    if (tid == 0) {
        float ss = 0.f;
#pragma unroll
        for (int w = 0; w < 8; w++) ss += red[w];
        bcast = 1.f / ss;
    }
    __syncthreads();
    const float inv = bcast;
#pragma unroll
    for (int j = 0; j < 16; j++) base[tid + j * 256] = vals[j] * inv;
}

__global__ __launch_bounds__(256) void zero_ctx_kernel()
{
    int i = blockIdx.x * 256 + threadIdx.x;
    if (i < BATCH * HEADS * DH * DH) g_ctx[i] = 0.f;
}

// ---------------------------------------------------------------------------
// context[b,h,d,e] += sum_{n in chunk} k_sm[d,n] * (v[e,n]/N)
// ---------------------------------------------------------------------------
__global__ __launch_bounds__(256) void context_kernel()
{
    const int nchunk = blockIdx.x;
    const int h = blockIdx.y;
    const int b = blockIdx.z;
    const float* kbase = g_qkv + ((size_t)b * OCQKV + INNER     + h * DH) * NPIX;
    const float* vbase = g_qkv + ((size_t)b * OCQKV + 2 * INNER + h * DH) * NPIX;

    __shared__ float Ks[64][65];   // [n][d]
    __shared__ float Vs[64][65];   // [n][e]

    const int tid = threadIdx.x;
    const int ty = tid >> 4, tx = tid & 15;
    float acc[4][4];
#pragma unroll
    for (int i = 0; i < 4; i++)
#pragma unroll
        for (int j = 0; j < 4; j++) acc[i][j] = 0.f;

    for (int nt = 0; nt < 8; nt++) {
        const int n0 = nchunk * 512 + nt * 64;
#pragma unroll
        for (int it = 0; it < 4; it++) {
            int idx = tid + it * 256;
            int r  = idx >> 4;            // 0..63 (d or e)
            int c4 = (idx & 15) * 4;      // n offset
            float4 kv = *reinterpret_cast<const float4*>(&kbase[(size_t)r * NPIX + n0 + c4]);
            Ks[c4 + 0][r] = kv.x; Ks[c4 + 1][r] = kv.y;
            Ks[c4 + 2][r] = kv.z; Ks[c4 + 3][r] = kv.w;
            float4 vv = *reinterpret_cast<const float4*>(&vbase[(size_t)r * NPIX + n0 + c4]);
            Vs[c4 + 0][r] = vv.x * INV_N; Vs[c4 + 1][r] = vv.y * INV_N;
            Vs[c4 + 2][r] = vv.z * INV_N; Vs[c4 + 3][r] = vv.w * INV_N;
        }
        __syncthreads();
#pragma unroll
        for (int nn = 0; nn < 64; nn++) {
            float kr[4], vr[4];
#pragma unroll
            for (int i = 0; i < 4; i++) kr[i] = Ks[nn][ty * 4 + i];
#pragma unroll
            for (int j = 0; j < 4; j++) vr[j] = Vs[nn][tx * 4 + j];
#pragma unroll
            for (int i = 0; i < 4; i++)
#pragma unroll
                for (int j = 0; j < 4; j++) acc[i][j] += kr[i] * vr[j];
        }
        __syncthreads();
    }
    float* cbase = g_ctx + (size_t)(b * HEADS + h) * DH * DH;
#pragma unroll
    for (int i = 0; i < 4; i++)
#pragma unroll
        for (int j = 0; j < 4; j++)
            atomicAdd(&cbase[(ty * 4 + i) * DH + tx * 4 + j], acc[i][j]);
}

// ---------------------------------------------------------------------------
// Fused softmax_q + apply:
// q_sm[d] = softmax_d(q[d]) / 8 (two-pass, reload hits L1/L2)
// out_mid[b, h*64+e, n] = sum_d ctx[b,h,d,e] * q_sm[d,n]
// ---------------------------------------------------------------------------
__global__ __launch_bounds__(256) void apply_kernel()
{
    const int n = blockIdx.x * 256 + threadIdx.x;
    const int h = blockIdx.y;
    const int b = blockIdx.z;

    __shared__ float ctxs[64][64];
    const float* csrc = g_ctx + (size_t)(b * HEADS + h) * DH * DH;
    for (int i = threadIdx.x; i < 4096; i += 256)
        (&ctxs[0][0])[i] = csrc[i];
    __syncthreads();

    const float* qbase = g_qkv + ((size_t)b * OCQKV + h * DH) * NPIX + n;

    // pass 1: softmax stats over d
    float mx = -CUDART_INF_F;
#pragma unroll 8
    for (int d = 0; d < 64; d++) mx = fmaxf(mx, qbase[(size_t)d * NPIX]);
    float s = 0.f;
#pragma unroll 8
    for (int d = 0; d < 64; d++) s += __expf(qbase[(size_t)d * NPIX] - mx);
    const float inv = 1.f / (s * 8.f);   // includes 1/sqrt(DH)

    // pass 2: apply
    float acc[64];
#pragma unroll
    for (int e = 0; e < 64; e++) acc[e] = 0.f;
#pragma unroll 4
    for (int d = 0; d < 64; d++) {
        float qd = __expf(qbase[(size_t)d * NPIX] - mx) * inv;
#pragma unroll
        for (int e = 0; e < 64; e++) acc[e] += ctxs[d][e] * qd;
    }
    float* obase = g_mid + ((size_t)b * INNER + h * DH) * NPIX + n;
#pragma unroll
    for (int e = 0; e < 64; e++) obase[(size_t)e * NPIX] = acc[e];
}

// ---------------------------------------------------------------------------
// LayerNorm over channel dim (512, stride N), no affine, eps=1e-5.
// ---------------------------------------------------------------------------
__global__ __launch_bounds__(256) void ln_kernel(float* __restrict__ out)
{
    const int n = blockIdx.x * 256 + threadIdx.x;
    const int b = blockIdx.y;
    const float* base = g_proj + (size_t)b * INNER * NPIX + n;

    float s = 0.f, s2 = 0.f;
#pragma unroll 8
    for (int c = 0; c < 512; c++) {
        float v = base[(size_t)c * NPIX];
        s += v; s2 += v * v;
    }
    const float mu  = s * (1.f / 512.f);
    const float var = s2 * (1.f / 512.f) - mu * mu;
    const float inv = rsqrtf(var + 1e-5f);
    float* ob = out + (size_t)b * INNER * NPIX + n;
#pragma unroll 8
    for (int c = 0; c < 512; c++)
        ob[(size_t)c * NPIX] = (base[(size_t)c * NPIX] - mu) * inv;
}

// ---------------------------------------------------------------------------
extern "C" void kernel_launch(void* const* d_in, const int* in_sizes, int n_in,
                              void* d_out, int out_size)
{
    (void)in_sizes; (void)n_in; (void)out_size;
    const float* x     = (const float*)d_in[0];   // [8,512,64,64]
    const float* w_qkv = (const float*)d_in[1];   // [1536,512]
    const float* w_out = (const float*)d_in[2];   // [512,512]
    const float* b_out = (const float*)d_in[3];   // [512]
    float* out = (float*)d_out;                   // [8,512,64,64]

    float* qkv_p;  cudaGetSymbolAddress((void**)&qkv_p,  g_qkv);
    float* mid_p;  cudaGetSymbolAddress((void**)&mid_p,  g_mid);
    float* proj_p; cudaGetSymbolAddress((void**)&proj_p, g_proj);
    float* wqkvt_p; cudaGetSymbolAddress((void**)&wqkvt_p, g_wqkv_t);
    float* woutt_p; cudaGetSymbolAddress((void**)&woutt_p, g_wout_t);

    // Pre-transpose weights: [M,K] -> [K,M]
    transpose_kernel<<<dim3(CIN / 32, OCQKV / 32), dim3(32, 8)>>>(
        w_qkv, wqkvt_p, OCQKV, CIN);
    transpose_kernel<<<dim3(INNER / 32, INNER / 32), dim3(32, 8)>>>(
        w_out, woutt_p, INNER, INNER);
    zero_ctx_kernel<<<(BATCH * HEADS * DH * DH + 255) / 256, 256>>>();

    // qkv = w_qkv @ x  : M=1536, K=512, N=4096 per batch
    gemm_tf32_pipe<<<dim3(NPIX / 128, OCQKV / 128, BATCH), 256>>>(
        wqkvt_p, x, qkv_p, OCQKV, CIN, NPIX, nullptr);
    softmax_k_kernel<<<BATCH * INNER, 256>>>();
    context_kernel<<<dim3(8, HEADS, BATCH), 256>>>();
    apply_kernel<<<dim3(NPIX / 256, HEADS, BATCH), 256>>>();
    // proj = w_out @ mid + b_out : M=512, K=512, N=4096 per batch
    gemm_tf32_pipe<<<dim3(NPIX / 128, INNER / 128, BATCH), 256>>>(
        woutt_p, mid_p, proj_p, INNER, INNER, NPIX, b_out);
    ln_kernel<<<dim3(NPIX / 256, BATCH), 256>>>(out);
}

// round 10
// speedup vs baseline: 2.7822x; 1.0028x over previous
#include <cuda_runtime.h>
#include <cuda_bf16.h>
#include <math_constants.h>
#include <cstdint>

// Problem constants
#define BATCH 8
#define CIN   512
#define NPIX  4096          // 64*64
#define OCQKV 1536          // 3 * INNER
#define INNER 512
#define HEADS 8
#define DH    64
#define INV_N (1.0f/4096.0f)

// Scratch (allocation-free: __device__ globals)
__device__ __align__(16) float g_qkv [(size_t)BATCH * OCQKV * NPIX];  // 192 MB
__device__ __align__(16) float g_ctx [(size_t)BATCH * HEADS * DH * DH]; // 1 MB
__device__ __align__(16) float g_mid [(size_t)BATCH * INNER * NPIX];  // 64 MB
__device__ __align__(16) float g_proj[(size_t)BATCH * INNER * NPIX];  // 64 MB
__device__ __align__(16) float g_wqkv_t[(size_t)CIN * OCQKV];         // 3 MB  [K,M]
__device__ __align__(16) float g_wout_t[(size_t)INNER * INNER];       // 1 MB  [K,M]

// ---------------------------------------------------------------------------
__device__ __forceinline__ void cp_async16(void* smem, const void* gmem) {
    uint32_t s = (uint32_t)__cvta_generic_to_shared(smem);
    asm volatile("cp.async.cg.shared.global [%0], [%1], 16;" :: "r"(s), "l"(gmem));
}

__device__ __forceinline__ void mma_tf32(float* c, const uint32_t* a, const uint32_t* b) {
    asm volatile(
        "mma.sync.aligned.m16n8k8.row.col.f32.tf32.tf32.f32 "
        "{%0,%1,%2,%3}, {%4,%5,%6,%7}, {%8,%9}, {%0,%1,%2,%3};\n"
        : "+f"(c[0]), "+f"(c[1]), "+f"(c[2]), "+f"(c[3])
        : "r"(a[0]), "r"(a[1]), "r"(a[2]), "r"(a[3]), "r"(b[0]), "r"(b[1]));
}

// ---------------------------------------------------------------------------
// 32x32-tiled transpose: out[c][r] = in[r][c]. block (32,8).
// ---------------------------------------------------------------------------
__global__ __launch_bounds__(256) void transpose_kernel(
    const float* __restrict__ in, float* __restrict__ out, int R, int C)
{
    __shared__ float t[32][33];
    const int r0 = blockIdx.y * 32, c0 = blockIdx.x * 32;
    const int x = threadIdx.x, y = threadIdx.y;
#pragma unroll
    for (int i = 0; i < 32; i += 8)
        t[y + i][x] = in[(size_t)(r0 + y + i) * C + c0 + x];
    __syncthreads();
#pragma unroll
    for (int i = 0; i < 32; i += 8)
        out[(size_t)(c0 + y + i) * R + r0 + x] = t[x][y + i];
}

// ---------------------------------------------------------------------------
// 4-stage pipelined tf32 GEMM: Y[b] = A(MxK) * X[b](KxN) (+bias).
// A supplied TRANSPOSED as At[K][M]. BM=BN=128, BK=16, 4-stage cp.async ring,
// ONE __syncthreads per K-iter. 8 warps (4x2), warp tile 32x64, mma m16n8k8.
// fp32 bits fed directly to HMMA.TF32. Smem stride 136 -> conflict-free LDS.
// Requires K % 16 == 0 and K/16 >= 3 (true here: K=512 -> NIT=32).
// ---------------------------------------------------------------------------
__global__ __launch_bounds__(256) void gemm_tf32_pipe(
    const float* __restrict__ At,  // [K,M]
    const float* __restrict__ Xg,  // [BATCH][K][N]
    float* __restrict__ Yg,        // [BATCH][M][N]
    int M, int K, int Nn,
    const float* __restrict__ bias)
{
    const int b  = blockIdx.z;
    const float* X = Xg + (size_t)b * K * Nn;
    float* Y       = Yg + (size_t)b * M * Nn;
    const int m0 = blockIdx.y * 128;
    const int n0 = blockIdx.x * 128;
    const int tid  = threadIdx.x;
    const int lane = tid & 31;
    const int warp = tid >> 5;
    const int wm = (warp & 3) * 32;   // 4 warps along M
    const int wn = (warp >> 2) * 64;  // 2 warps along N
    const int r = lane >> 2;          // 0..7
    const int c = lane & 3;           // 0..3

    __shared__ float As[4][16][136];  // [k][m]
    __shared__ float Bs[4][16][136];  // [k][n]

    const int NIT = K >> 4;           // K/16

    float acc[2][8][4];
#pragma unroll
    for (int mt = 0; mt < 2; mt++)
#pragma unroll
        for (int nt = 0; nt < 8; nt++)
#pragma unroll
            for (int i = 0; i < 4; i++) acc[mt][nt][i] = 0.f;

    // per-thread copy coordinates: 2 float4 per tile per thread
    const int kk0 = tid >> 5;         // 0..7
    const int c4  = (lane) * 4;       // 0..124

    // prologue: stages 0,1,2
#pragma unroll
    for (int s = 0; s < 3; s++) {
        const float* a_src = At + (size_t)s * 16 * M  + m0;
        const float* b_src = X  + (size_t)s * 16 * Nn + n0;
#pragma unroll
        for (int u = 0; u < 2; u++) {
            int kk = kk0 + u * 8;
            cp_async16(&As[s][kk][c4], a_src + (size_t)kk * M  + c4);
            cp_async16(&Bs[s][kk][c4], b_src + (size_t)kk * Nn + c4);
        }
        asm volatile("cp.async.commit_group;");
    }

    for (int it = 0; it < NIT; it++) {
        asm volatile("cp.async.wait_group 2;");
        __syncthreads();

        // issue stage it+3 (buffer freed at iter it-1; barrier above protects)
        if (it + 3 < NIT) {
            const int sb = (it + 3) & 3;
            const float* a_src = At + (size_t)(it + 3) * 16 * M  + m0;
            const float* b_src = X  + (size_t)(it + 3) * 16 * Nn + n0;
#pragma unroll
            for (int u = 0; u < 2; u++) {
                int kk = kk0 + u * 8;
                cp_async16(&As[sb][kk][c4], a_src + (size_t)kk * M  + c4);
                cp_async16(&Bs[sb][kk][c4], b_src + (size_t)kk * Nn + c4);
            }
        }
        asm volatile("cp.async.commit_group;");   // unconditional: keeps group count uniform

        const int cb = it & 3;
#pragma unroll
        for (int ks = 0; ks < 2; ks++) {
            const int kc = ks * 8;
            uint32_t af[2][4];
#pragma unroll
            for (int mt = 0; mt < 2; mt++) {
                int mb = wm + mt * 16 + r;
                af[mt][0] = __float_as_uint(As[cb][kc + c][mb]);
                af[mt][1] = __float_as_uint(As[cb][kc + c][mb + 8]);
                af[mt][2] = __float_as_uint(As[cb][kc + c + 4][mb]);
                af[mt][3] = __float_as_uint(As[cb][kc + c + 4][mb + 8]);
            }
            uint32_t bf[8][2];
#pragma unroll
            for (int nt = 0; nt < 8; nt++) {
                int nb2 = wn + nt * 8 + r;
                bf[nt][0] = __float_as_uint(Bs[cb][kc + c][nb2]);
                bf[nt][1] = __float_as_uint(Bs[cb][kc + c + 4][nb2]);
            }
#pragma unroll
            for (int mt = 0; mt < 2; mt++)
#pragma unroll
                for (int nt = 0; nt < 8; nt++)
                    mma_tf32(acc[mt][nt], af[mt], bf[nt]);
        }
    }

    __syncthreads();   // protect smem reuse vs. any residual cp.async (none) before exit

    // Epilogue: c0,c1 -> (row, 2c), (row, 2c+1); c2,c3 -> row+8.
#pragma unroll
    for (int mt = 0; mt < 2; mt++) {
        const int mrow = m0 + wm + mt * 16 + r;
        const float bv0 = bias ? bias[mrow]     : 0.f;
        const float bv1 = bias ? bias[mrow + 8] : 0.f;
#pragma unroll
        for (int nt = 0; nt < 8; nt++) {
            const int ncol = n0 + wn + nt * 8 + 2 * c;
            float2 o0, o1;
            o0.x = acc[mt][nt][0] + bv0; o0.y = acc[mt][nt][1] + bv0;
            o1.x = acc[mt][nt][2] + bv1; o1.y = acc[mt][nt][3] + bv1;
            *reinterpret_cast<float2*>(&Y[(size_t)mrow * Nn + ncol]) = o0;
            *reinterpret_cast<float2*>(&Y[(size_t)(mrow + 8) * Nn + ncol]) = o1;
        }
    }
}

// ---------------------------------------------------------------------------
// softmax over N (4096 contiguous) for the k block. One block per row.
// ---------------------------------------------------------------------------
__global__ __launch_bounds__(256) void softmax_k_kernel()
{
    const int row = blockIdx.x;        // 0..4095 = b*512 + ch
    const int b   = row >> 9;
    const int ch  = row & 511;
    float* base = g_qkv + ((size_t)b * OCQKV + INNER + ch) * NPIX;
    const int tid = threadIdx.x;
    const int lane = tid & 31, wid = tid >> 5;

    __shared__ float red[8];
    __shared__ float bcast;

    float vals[16];
#pragma unroll
    for (int j = 0; j < 16; j++) vals[j] = base[tid + j * 256];

    float m = vals[0];
#pragma unroll
    for (int j = 1; j < 16; j++) m = fmaxf(m, vals[j]);
#pragma unroll
    for (int off = 16; off > 0; off >>= 1)
        m = fmaxf(m, __shfl_xor_sync(0xffffffff, m, off));
    if (lane == 0) red[wid] = m;
    __syncthreads();
    if (tid == 0) {
        float mm = red[0];
#pragma unroll
        for (int w = 1; w < 8; w++) mm = fmaxf(mm, red[w]);
        bcast = mm;
    }
    __syncthreads();
    const float mx = bcast;

    float s = 0.f;
#pragma unroll
    for (int j = 0; j < 16; j++) { vals[j] = __expf(vals[j] - mx); s += vals[j]; }
#pragma unroll
    for (int off = 16; off > 0; off >>= 1)
        s += __shfl_xor_sync(0xffffffff, s, off);
    if (lane == 0) red[wid] = s;
    __syncthreads();
    if (tid == 0) {
        float ss = 0.f;
#pragma unroll
        for (int w = 0; w < 8; w++) ss += red[w];
        bcast = 1.f / ss;
    }
    __syncthreads();
    const float inv = bcast;
#pragma unroll
    for (int j = 0; j < 16; j++) base[tid + j * 256] = vals[j] * inv;
}

__global__ __launch_bounds__(256) void zero_ctx_kernel()
{
    int i = blockIdx.x * 256 + threadIdx.x;
    if (i < BATCH * HEADS * DH * DH) g_ctx[i] = 0.f;
}

// ---------------------------------------------------------------------------
// context[b,h,d,e] += sum_{n in chunk} k_sm[d,n] * (v[e,n]/N)
// ---------------------------------------------------------------------------
__global__ __launch_bounds__(256) void context_kernel()
{
    const int nchunk = blockIdx.x;
    const int h = blockIdx.y;
    const int b = blockIdx.z;
    const float* kbase = g_qkv + ((size_t)b * OCQKV + INNER     + h * DH) * NPIX;
    const float* vbase = g_qkv + ((size_t)b * OCQKV + 2 * INNER + h * DH) * NPIX;

    __shared__ float Ks[64][65];   // [n][d]
    __shared__ float Vs[64][65];   // [n][e]

    const int tid = threadIdx.x;
    const int ty = tid >> 4, tx = tid & 15;
    float acc[4][4];
#pragma unroll
    for (int i = 0; i < 4; i++)
#pragma unroll
        for (int j = 0; j < 4; j++) acc[i][j] = 0.f;

    for (int nt = 0; nt < 8; nt++) {
        const int n0 = nchunk * 512 + nt * 64;
#pragma unroll
        for (int it = 0; it < 4; it++) {
            int idx = tid + it * 256;
            int r  = idx >> 4;            // 0..63 (d or e)
            int c4 = (idx & 15) * 4;      // n offset
            float4 kv = *reinterpret_cast<const float4*>(&kbase[(size_t)r * NPIX + n0 + c4]);
            Ks[c4 + 0][r] = kv.x; Ks[c4 + 1][r] = kv.y;
            Ks[c4 + 2][r] = kv.z; Ks[c4 + 3][r] = kv.w;
            float4 vv = *reinterpret_cast<const float4*>(&vbase[(size_t)r * NPIX + n0 + c4]);
            Vs[c4 + 0][r] = vv.x * INV_N; Vs[c4 + 1][r] = vv.y * INV_N;
            Vs[c4 + 2][r] = vv.z * INV_N; Vs[c4 + 3][r] = vv.w * INV_N;
        }
        __syncthreads();
#pragma unroll
        for (int nn = 0; nn < 64; nn++) {
            float kr[4], vr[4];
#pragma unroll
            for (int i = 0; i < 4; i++) kr[i] = Ks[nn][ty * 4 + i];
#pragma unroll
            for (int j = 0; j < 4; j++) vr[j] = Vs[nn][tx * 4 + j];
#pragma unroll
            for (int i = 0; i < 4; i++)
#pragma unroll
                for (int j = 0; j < 4; j++) acc[i][j] += kr[i] * vr[j];
        }
        __syncthreads();
    }
    float* cbase = g_ctx + (size_t)(b * HEADS + h) * DH * DH;
#pragma unroll
    for (int i = 0; i < 4; i++)
#pragma unroll
        for (int j = 0; j < 4; j++)
            atomicAdd(&cbase[(ty * 4 + i) * DH + tx * 4 + j], acc[i][j]);
}

// ---------------------------------------------------------------------------
// Fused softmax_q + apply:
// q_sm[d] = softmax_d(q[d]) / 8 (two-pass, reload hits L1/L2)
// out_mid[b, h*64+e, n] = sum_d ctx[b,h,d,e] * q_sm[d,n]
// ---------------------------------------------------------------------------
__global__ __launch_bounds__(256) void apply_kernel()
{
    const int n = blockIdx.x * 256 + threadIdx.x;
    const int h = blockIdx.y;
    const int b = blockIdx.z;

    __shared__ float ctxs[64][64];
    const float* csrc = g_ctx + (size_t)(b * HEADS + h) * DH * DH;
    for (int i = threadIdx.x; i < 4096; i += 256)
        (&ctxs[0][0])[i] = csrc[i];
    __syncthreads();

    const float* qbase = g_qkv + ((size_t)b * OCQKV + h * DH) * NPIX + n;

    // pass 1: softmax stats over d
    float mx = -CUDART_INF_F;
#pragma unroll 8
    for (int d = 0; d < 64; d++) mx = fmaxf(mx, qbase[(size_t)d * NPIX]);
    float s = 0.f;
#pragma unroll 8
    for (int d = 0; d < 64; d++) s += __expf(qbase[(size_t)d * NPIX] - mx);
    const float inv = 1.f / (s * 8.f);   // includes 1/sqrt(DH)

    // pass 2: apply
    float acc[64];
#pragma unroll
    for (int e = 0; e < 64; e++) acc[e] = 0.f;
#pragma unroll 4
    for (int d = 0; d < 64; d++) {
        float qd = __expf(qbase[(size_t)d * NPIX] - mx) * inv;
#pragma unroll
        for (int e = 0; e < 64; e++) acc[e] += ctxs[d][e] * qd;
    }
    float* obase = g_mid + ((size_t)b * INNER + h * DH) * NPIX + n;
#pragma unroll
    for (int e = 0; e < 64; e++) obase[(size_t)e * NPIX] = acc[e];
}

// ---------------------------------------------------------------------------
// Single-sweep LayerNorm over channel dim (512, stride NPIX), eps=1e-5.
// Block = 32 pixels; tile [512 ch][32 px] staged in smem (one global read).
// ---------------------------------------------------------------------------
__global__ __launch_bounds__(256) void ln_kernel(float* __restrict__ out)
{
    const int n0 = blockIdx.x * 32;
    const int b  = blockIdx.y;
    const int tid = threadIdx.x;
    const int p = tid & 31;       // pixel within tile (lane)
    const int g = tid >> 5;       // channel group (warp)

    __shared__ float s[512][33];
    __shared__ float psum[8][33], psum2[8][33];
    __shared__ float smu[32], sinv[32];

    const float* base = g_proj + (size_t)b * INNER * NPIX + n0;
#pragma unroll 4
    for (int idx = tid; idx < 512 * 32; idx += 256) {
        int cc = idx >> 5, pp = idx & 31;
        s[cc][pp] = base[(size_t)cc * NPIX + pp];
    }
    __syncthreads();

    // warp g sums channels [g*64, g*64+64) for pixel p
    float sum = 0.f, sum2 = 0.f;
#pragma unroll 8
    for (int j = 0; j < 64; j++) {
        float v = s[g * 64 + j][p];
        sum += v; sum2 += v * v;
    }
    psum[g][p] = sum; psum2[g][p] = sum2;
    __syncthreads();

    if (tid < 32) {
        float ts = 0.f, ts2 = 0.f;
#pragma unroll
        for (int w = 0; w < 8; w++) { ts += psum[w][tid]; ts2 += psum2[w][tid]; }
        const float mu  = ts * (1.f / 512.f);
        const float var = ts2 * (1.f / 512.f) - mu * mu;
        smu[tid]  = mu;
        sinv[tid] = rsqrtf(var + 1e-5f);
    }
    __syncthreads();

    float* ob = out + (size_t)b * INNER * NPIX + n0;
#pragma unroll 4
    for (int idx = tid; idx < 512 * 32; idx += 256) {
        int cc = idx >> 5, pp = idx & 31;
        ob[(size_t)cc * NPIX + pp] = (s[cc][pp] - smu[pp]) * sinv[pp];
    }
}

// ---------------------------------------------------------------------------
extern "C" void kernel_launch(void* const* d_in, const int* in_sizes, int n_in,
                              void* d_out, int out_size)
{
    (void)in_sizes; (void)n_in; (void)out_size;
    const float* x     = (const float*)d_in[0];   // [8,512,64,64]
    const float* w_qkv = (const float*)d_in[1];   // [1536,512]
    const float* w_out = (const float*)d_in[2];   // [512,512]
    const float* b_out = (const float*)d_in[3];   // [512]
    float* out = (float*)d_out;                   // [8,512,64,64]

    float* qkv_p;  cudaGetSymbolAddress((void**)&qkv_p,  g_qkv);
    float* mid_p;  cudaGetSymbolAddress((void**)&mid_p,  g_mid);
    float* proj_p; cudaGetSymbolAddress((void**)&proj_p, g_proj);
    float* wqkvt_p; cudaGetSymbolAddress((void**)&wqkvt_p, g_wqkv_t);
    float* woutt_p; cudaGetSymbolAddress((void**)&woutt_p, g_wout_t);

    // Pre-transpose weights: [M,K] -> [K,M]
    transpose_kernel<<<dim3(CIN / 32, OCQKV / 32), dim3(32, 8)>>>(
        w_qkv, wqkvt_p, OCQKV, CIN);
    transpose_kernel<<<dim3(INNER / 32, INNER / 32), dim3(32, 8)>>>(
        w_out, woutt_p, INNER, INNER);
    zero_ctx_kernel<<<(BATCH * HEADS * DH * DH + 255) / 256, 256>>>();

    // qkv = w_qkv @ x  : M=1536, K=512, N=4096 per batch
    gemm_tf32_pipe<<<dim3(NPIX / 128, OCQKV / 128, BATCH), 256>>>(
        wqkvt_p, x, qkv_p, OCQKV, CIN, NPIX, nullptr);
    softmax_k_kernel<<<BATCH * INNER, 256>>>();
    context_kernel<<<dim3(8, HEADS, BATCH), 256>>>();
    apply_kernel<<<dim3(NPIX / 256, HEADS, BATCH), 256>>>();
    // proj = w_out @ mid + b_out : M=512, K=512, N=4096 per batch
    gemm_tf32_pipe<<<dim3(NPIX / 128, INNER / 128, BATCH), 256>>>(
        woutt_p, mid_p, proj_p, INNER, INNER, NPIX, b_out);
    ln_kernel<<<dim3(NPIX / 32, BATCH), 256>>>(out);
}